// round 11
// baseline (speedup 1.0000x reference)
#include <cuda_runtime.h>
#include <cuda_bf16.h>
#include <cstdint>

#define B_ROWS 32768
#define C_COLS 1000
#define C_PAD  1024
#define F_DIM  256

#define BMR     32      // feature rows per CTA
#define BNP     256     // proto cols per CTA (cluster of 4 covers 1024)
#define NKC     4       // 256 / 64 k-chunks
#define THREADS 256     // 8 warps
#define CLSZ    4

// SMEM layout (bytes)
#define SM_FEAT  0                        // 32 rows x 512B swizzled      = 16KB
#define SM_SROW  16384                    // 32 floats (own partial sums)
#define SM_SMEAN 16512                    // 32 floats (cluster means)
#define SM_B0    17408                    // proto chunk: 256 x 128B      = 32KB
#define SM_B1    (17408 + 32768)
#define SM_STAGE 17408                    // reuses B0: 32 x 1024B        = 32KB
#define SM_TOTAL (17408 + 65536)          // 82944  (x2 CTAs = 162KB/SM)

// Scratch (device global — no allocation allowed)
__device__ __align__(16) __nv_bfloat16 g_Pn[(size_t)C_PAD * F_DIM];

// ---------------------------------------------------------------------------
// helpers
// ---------------------------------------------------------------------------
__device__ __forceinline__ uint32_t smem_u32(const void* p) {
    uint32_t a;
    asm("{ .reg .u64 t; cvta.to.shared.u64 t, %1; cvt.u32.u64 %0, t; }" : "=r"(a) : "l"(p));
    return a;
}
__device__ __forceinline__ void ldsm_x4(uint32_t* r, uint32_t addr) {
    asm volatile("ldmatrix.sync.aligned.m8n8.x4.shared.b16 {%0,%1,%2,%3}, [%4];\n"
        : "=r"(r[0]), "=r"(r[1]), "=r"(r[2]), "=r"(r[3]) : "r"(addr));
}
__device__ __forceinline__ void mma16816(float* c, const uint32_t* a, uint32_t b0, uint32_t b1) {
    asm volatile(
        "mma.sync.aligned.m16n8k16.row.col.f32.bf16.bf16.f32 "
        "{%0,%1,%2,%3}, {%4,%5,%6,%7}, {%8,%9}, {%0,%1,%2,%3};\n"
        : "+f"(c[0]), "+f"(c[1]), "+f"(c[2]), "+f"(c[3])
        : "r"(a[0]), "r"(a[1]), "r"(a[2]), "r"(a[3]), "r"(b0), "r"(b1));
}
__device__ __forceinline__ float fsqrt_ap(float x) {
    float r; asm("sqrt.approx.f32 %0, %1;" : "=f"(r) : "f"(x)); return r;
}
#define CP_ASYNC16(dst, src) \
    asm volatile("cp.async.cg.shared.global [%0], [%1], 16;" :: "r"(dst), "l"(src))
#define CP_COMMIT() asm volatile("cp.async.commit_group;" ::: "memory")
#define CP_WAIT0()  asm volatile("cp.async.wait_group 0;" ::: "memory")
#define CLUSTER_ARRIVE() asm volatile("barrier.cluster.arrive.aligned;" ::: "memory")
#define CLUSTER_WAIT()   asm volatile("barrier.cluster.wait.aligned;" ::: "memory")

// ---------------------------------------------------------------------------
// Kernel 1: L2-normalize prototypes -> bf16, zero-pad rows [1000,1024)
// ---------------------------------------------------------------------------
__global__ void norm_protos_kernel(const float* __restrict__ proto) {
    int gtid = blockIdx.x * blockDim.x + threadIdx.x;
    int row  = gtid >> 5;
    int lane = gtid & 31;
    if (row >= C_PAD) return;

    if (row >= C_COLS) {
        uint4 z = {0u, 0u, 0u, 0u};
        reinterpret_cast<uint4*>(g_Pn)[row * (F_DIM/8) + lane] = z;
        return;
    }
    const float4* src = reinterpret_cast<const float4*>(proto + (size_t)row * F_DIM);
    float4 v0 = src[lane * 2 + 0];
    float4 v1 = src[lane * 2 + 1];

    float ss = v0.x*v0.x + v0.y*v0.y + v0.z*v0.z + v0.w*v0.w
             + v1.x*v1.x + v1.y*v1.y + v1.z*v1.z + v1.w*v1.w;
    #pragma unroll
    for (int o = 16; o; o >>= 1) ss += __shfl_xor_sync(0xFFFFFFFFu, ss, o);
    float inv = 1.0f / fmaxf(sqrtf(ss), 1e-12f);

    union { __nv_bfloat162 h[4]; uint4 u; } pack;
    pack.h[0] = __floats2bfloat162_rn(v0.x*inv, v0.y*inv);
    pack.h[1] = __floats2bfloat162_rn(v0.z*inv, v0.w*inv);
    pack.h[2] = __floats2bfloat162_rn(v1.x*inv, v1.y*inv);
    pack.h[3] = __floats2bfloat162_rn(v1.z*inv, v1.w*inv);
    reinterpret_cast<uint4*>(g_Pn)[row * (F_DIM/8) + lane] = pack.u;
}

// ---------------------------------------------------------------------------
// Kernel 2: fused normalize(A) + GEMM + epilogue. 4-CTA cluster per row block,
// 2 CTAs/SM for latency hiding (256 threads, ~96 regs, 81KB smem each).
//   CTA = 32 feat rows x 256 protos. Warp w (0..7): protos [w*32,+32) x all 32
//   feats; acc[2][4][4] = 32 regs. Protos = A-operand (m16), feats = B (n8).
//   Feats normalized in-CTA, full-K resident (16KB). Protos streamed in 4
//   k64-chunks (32KB each, double-buffered cp.async).
//   Row means: per-CTA partials summed across 4 cluster ranks via DSMEM.
// ---------------------------------------------------------------------------
__global__ void __launch_bounds__(THREADS, 2) __cluster_dims__(CLSZ, 1, 1)
fused_gemm_kernel(const float* __restrict__ feat,
                  const float* __restrict__ dscale, const float* __restrict__ temp,
                  float* __restrict__ out) {
    extern __shared__ __align__(16) unsigned char smem[];
    const uint32_t smem_base = smem_u32(smem);

    const int tid  = threadIdx.x;
    const int lane = tid & 31;
    const int warp = tid >> 5;
    const int gp0  = blockIdx.x * BNP;           // proto base (rank * 256)
    const int grow = blockIdx.y * BMR;           // feature row base

    float* srow  = reinterpret_cast<float*>(smem + SM_SROW);
    float* smean = reinterpret_cast<float*>(smem + SM_SMEAN);
    if (tid < BMR) srow[tid] = 0.0f;

    // ---- Prefetch proto k-chunk 0 (overlaps feature normalize) ----
    const uint4* gB = reinterpret_cast<const uint4*>(g_Pn);
    {
        #pragma unroll
        for (int it = 0; it < 8; it++) {
            int idx = it * THREADS + tid;        // 0..2047
            int r = idx >> 3, c8 = idx & 7;
            uint32_t dst = smem_base + SM_B0 + r * 128 + ((c8 ^ (r & 7)) << 4);
            CP_ASYNC16(dst, gB + (size_t)(gp0 + r) * 32 + c8);
        }
        CP_COMMIT();
    }

    // ---- Normalize feature rows in-CTA: warp w -> rows 4w..4w+3 ----
    {
        const float4* gF = reinterpret_cast<const float4*>(feat)
                         + (size_t)grow * (F_DIM / 4);
        #pragma unroll
        for (int rr = 0; rr < 4; rr++) {
            int r = warp * 4 + rr;
            float4 v0 = __ldg(&gF[r * 64 + lane * 2 + 0]);
            float4 v1 = __ldg(&gF[r * 64 + lane * 2 + 1]);
            float ss = v0.x*v0.x + v0.y*v0.y + v0.z*v0.z + v0.w*v0.w
                     + v1.x*v1.x + v1.y*v1.y + v1.z*v1.z + v1.w*v1.w;
            #pragma unroll
            for (int o = 16; o; o >>= 1) ss += __shfl_xor_sync(0xFFFFFFFFu, ss, o);
            float inv = 1.0f / fmaxf(sqrtf(ss), 1e-12f);

            union { __nv_bfloat162 h[4]; uint4 u; } pack;
            pack.h[0] = __floats2bfloat162_rn(v0.x*inv, v0.y*inv);
            pack.h[1] = __floats2bfloat162_rn(v0.z*inv, v0.w*inv);
            pack.h[2] = __floats2bfloat162_rn(v1.x*inv, v1.y*inv);
            pack.h[3] = __floats2bfloat162_rn(v1.z*inv, v1.w*inv);
            *reinterpret_cast<uint4*>(smem + SM_FEAT + r * 512 + ((lane ^ (r & 7)) << 4)) = pack.u;
        }
    }
    CP_WAIT0();
    __syncthreads();

    // ---- addressing ----
    uint32_t pBase[2]; int pXor[2];
    #pragma unroll
    for (int pp = 0; pp < 2; pp++) {
        int prow = warp * 32 + pp * 16 + (lane & 15);
        pBase[pp] = prow * 128;
        pXor[pp]  = prow & 7;
    }
    const int p_h = lane >> 4;

    const int b_n = (lane & 7) | ((lane & 16) >> 1);
    const int b_h = (lane >> 3) & 1;
    uint32_t fBase[2]; int fXor[2];
    #pragma unroll
    for (int fq = 0; fq < 2; fq++) {
        int frow = fq * 16 + b_n;
        fBase[fq] = smem_base + SM_FEAT + frow * 512;
        fXor[fq]  = frow & 7;
    }

    float acc[2][4][4];
    #pragma unroll
    for (int pp = 0; pp < 2; pp++)
        #pragma unroll
        for (int ff = 0; ff < 4; ff++)
            #pragma unroll
            for (int i = 0; i < 4; i++) acc[pp][ff][i] = 0.0f;

    // ---- Main loop: 4 k64-chunks, double-buffered ----
    #pragma unroll
    for (int kc = 0; kc < NKC; kc++) {
        if (kc < NKC - 1) {
            uint32_t nb = smem_base + ((kc & 1) ? SM_B0 : SM_B1);
            #pragma unroll
            for (int it = 0; it < 8; it++) {
                int idx = it * THREADS + tid;
                int r = idx >> 3, c8 = idx & 7;
                CP_ASYNC16(nb + r * 128 + ((c8 ^ (r & 7)) << 4),
                           gB + (size_t)(gp0 + r) * 32 + (kc + 1) * 8 + c8);
            }
            CP_COMMIT();
        }

        uint32_t buf = smem_base + ((kc & 1) ? SM_B1 : SM_B0);

        #pragma unroll
        for (int kk = 0; kk < 4; kk++) {
            uint32_t ap[2][4], fb[2][4];
            #pragma unroll
            for (int pp = 0; pp < 2; pp++)
                ldsm_x4(ap[pp], buf + pBase[pp] + (((2 * kk + p_h) ^ pXor[pp]) << 4));
            int kg = kc * 4 + kk;
            #pragma unroll
            for (int fq = 0; fq < 2; fq++)
                ldsm_x4(fb[fq], fBase[fq] + (((2 * kg + b_h) ^ fXor[fq]) << 4));

            #pragma unroll
            for (int pp = 0; pp < 2; pp++)
                #pragma unroll
                for (int ff = 0; ff < 4; ff++) {
                    int fq = ff >> 1, h = (ff & 1) * 2;
                    mma16816(acc[pp][ff], ap[pp], fb[fq][h], fb[fq][h + 1]);
                }
        }

        if (kc < NKC - 1) {
            CP_WAIT0();
            __syncthreads();
        }
    }
    __syncthreads();   // all MMA done before B buffers are reused as stage

    // ---- Epilogue pass 1: iso + per-feature partial sums (masked protos) ----
    const float ads = fabsf(__ldg(dscale));
    const float it_ = 1.0f / __ldg(temp);

    bool v0[2], v1[2];
    #pragma unroll
    for (int pp = 0; pp < 2; pp++) {
        int P = gp0 + warp * 32 + pp * 16 + (lane >> 2);
        v0[pp] = (P < C_COLS);
        v1[pp] = (P + 8 < C_COLS);
    }

    #pragma unroll
    for (int ff = 0; ff < 4; ff++) {
        float s0 = 0.0f, s1 = 0.0f;
        #pragma unroll
        for (int pp = 0; pp < 2; pp++) {
            float i0 = ads * fsqrt_ap(fmaxf(1.0f - acc[pp][ff][0], 0.0f));
            float i1 = ads * fsqrt_ap(fmaxf(1.0f - acc[pp][ff][1], 0.0f));
            float i2 = ads * fsqrt_ap(fmaxf(1.0f - acc[pp][ff][2], 0.0f));
            float i3 = ads * fsqrt_ap(fmaxf(1.0f - acc[pp][ff][3], 0.0f));
            acc[pp][ff][0] = i0; acc[pp][ff][1] = i1;
            acc[pp][ff][2] = i2; acc[pp][ff][3] = i3;
            if (v0[pp]) { s0 += i0; s1 += i1; }
            if (v1[pp]) { s0 += i2; s1 += i3; }
        }
        s0 += __shfl_xor_sync(0xFFFFFFFFu, s0, 4);
        s0 += __shfl_xor_sync(0xFFFFFFFFu, s0, 8);
        s0 += __shfl_xor_sync(0xFFFFFFFFu, s0, 16);
        s1 += __shfl_xor_sync(0xFFFFFFFFu, s1, 4);
        s1 += __shfl_xor_sync(0xFFFFFFFFu, s1, 8);
        s1 += __shfl_xor_sync(0xFFFFFFFFu, s1, 16);
        if (lane < 4) {
            atomicAdd(&srow[ff * 8 + 2 * lane],     s0);
            atomicAdd(&srow[ff * 8 + 2 * lane + 1], s1);
        }
    }
    __syncthreads();

    // ---- Cluster-wide row-sum: each CTA reads all 4 ranks' partials ----
    CLUSTER_ARRIVE();
    CLUSTER_WAIT();
    if (tid < BMR) {
        uint32_t local = smem_base + SM_SROW + tid * 4;
        float total = 0.0f;
        #pragma unroll
        for (int j = 0; j < CLSZ; j++) {
            uint32_t rem;
            asm("mapa.shared::cluster.u32 %0, %1, %2;" : "=r"(rem) : "r"(local), "r"((uint32_t)j));
            float pv;
            asm volatile("ld.shared::cluster.f32 %0, [%1];" : "=f"(pv) : "r"(rem));
            total += pv;
        }
        smean[tid] = total * (1.0f / (float)C_COLS);
    }
    CLUSTER_ARRIVE();
    CLUSTER_WAIT();
    __syncthreads();

    // ---- Epilogue pass 2: logits -> swizzled stage ----
    // stage word(f, p) = f*256 + ((p + 4*(f&7)) & 255)
    float* stg = reinterpret_cast<float*>(smem + SM_STAGE);
    const int pl0 = warp * 32 + (lane >> 2);
    #pragma unroll
    for (int ff = 0; ff < 4; ff++) {
        int f0 = ff * 8 + 2 * (lane & 3);
        int f1 = f0 + 1;
        float m0 = smean[f0], m1 = smean[f1];
        #pragma unroll
        for (int pp = 0; pp < 2; pp++) {
            int p = pl0 + pp * 16;
            stg[f0 * 256 + ((p     + 4 * (f0 & 7)) & 255)] = -(acc[pp][ff][0] + m0) * it_;
            stg[f1 * 256 + ((p     + 4 * (f1 & 7)) & 255)] = -(acc[pp][ff][1] + m1) * it_;
            stg[f0 * 256 + ((p + 8 + 4 * (f0 & 7)) & 255)] = -(acc[pp][ff][2] + m0) * it_;
            stg[f1 * 256 + ((p + 8 + 4 * (f1 & 7)) & 255)] = -(acc[pp][ff][3] + m1) * it_;
        }
    }
    __syncthreads();

    // ---- Coalesced global write: 32 rows x (256 or 232) cols ----
    const int validP4 = (gp0 + BNP <= C_COLS) ? (BNP / 4) : ((C_COLS - gp0) / 4); // 64 or 58
    #pragma unroll
    for (int i = 0; i < 8; i++) {
        int fidx = i * THREADS + tid;    // 0..2047 over 32 rows x 64 f4
        int f  = fidx >> 6;
        int p4 = fidx & 63;
        if (p4 < validP4) {
            int pw = (4 * p4 + 4 * (f & 7)) & 255;   // 4-aligned word
            float4 v = *reinterpret_cast<float4*>(&stg[f * 256 + pw]);
            *reinterpret_cast<float4*>(out + (size_t)(grow + f) * C_COLS + gp0 + 4 * p4) = v;
        }
    }
}

// ---------------------------------------------------------------------------
extern "C" void kernel_launch(void* const* d_in, const int* in_sizes, int n_in,
                              void* d_out, int out_size) {
    const float* feat  = (const float*)d_in[0];
    const float* proto = (const float*)d_in[1];
    const float* dsc   = (const float*)d_in[2];
    const float* temp  = (const float*)d_in[3];
    float* out = (float*)d_out;

    cudaFuncSetAttribute(fused_gemm_kernel,
                         cudaFuncAttributeMaxDynamicSharedMemorySize, SM_TOTAL);

    norm_protos_kernel<<<C_PAD / 8, 256>>>(proto);
    fused_gemm_kernel<<<dim3(CLSZ, B_ROWS / BMR), THREADS, SM_TOTAL>>>(feat, dsc, temp, out);
}

// round 14
// speedup vs baseline: 1.2425x; 1.2425x over previous
#include <cuda_runtime.h>
#include <cuda_bf16.h>
#include <cstdint>

#define B_ROWS 32768
#define C_COLS 1000
#define C_PAD  1024
#define F_DIM  256

#define BM      32      // output rows per CTA
#define BNC     128     // B chunk rows (output cols) per stage
#define NCHUNK  8       // 1024 / 128
#define THREADS 512     // 16 warps

// SMEM layout (bytes)
#define SM_A     0                        // 32 rows x 512B swizzled  = 16KB
#define SM_SROW  16384                    // 32 floats row sums
#define SM_B0    17408                    // 128 x 512B = 64KB
#define SM_B1    (17408 + 65536)
#define SM_B2    (17408 + 131072)
#define SM_TOTAL (17408 + 196608)         // 214016 <= 227KB

// Scratch (device global — no allocation allowed)
__device__ __align__(16) __nv_bfloat16 g_Pn[(size_t)C_PAD * F_DIM];

// ---------------------------------------------------------------------------
// helpers
// ---------------------------------------------------------------------------
__device__ __forceinline__ uint32_t smem_u32(const void* p) {
    uint32_t a;
    asm("{ .reg .u64 t; cvta.to.shared.u64 t, %1; cvt.u32.u64 %0, t; }" : "=r"(a) : "l"(p));
    return a;
}
__device__ __forceinline__ void ldsm_x4(uint32_t* r, uint32_t addr) {
    asm volatile("ldmatrix.sync.aligned.m8n8.x4.shared.b16 {%0,%1,%2,%3}, [%4];\n"
        : "=r"(r[0]), "=r"(r[1]), "=r"(r[2]), "=r"(r[3]) : "r"(addr));
}
__device__ __forceinline__ void mma16816(float* c, const uint32_t* a, uint32_t b0, uint32_t b1) {
    asm volatile(
        "mma.sync.aligned.m16n8k16.row.col.f32.bf16.bf16.f32 "
        "{%0,%1,%2,%3}, {%4,%5,%6,%7}, {%8,%9}, {%0,%1,%2,%3};\n"
        : "+f"(c[0]), "+f"(c[1]), "+f"(c[2]), "+f"(c[3])
        : "r"(a[0]), "r"(a[1]), "r"(a[2]), "r"(a[3]), "r"(b0), "r"(b1));
}
__device__ __forceinline__ float fsqrt_ap(float x) {
    float r; asm("sqrt.approx.f32 %0, %1;" : "=f"(r) : "f"(x)); return r;
}
#define CP_ASYNC16(dst, src) \
    asm volatile("cp.async.cg.shared.global [%0], [%1], 16;" :: "r"(dst), "l"(src))
#define CP_COMMIT() asm volatile("cp.async.commit_group;" ::: "memory")
#define CP_WAIT0()  asm volatile("cp.async.wait_group 0;" ::: "memory")
#define CP_WAIT1()  asm volatile("cp.async.wait_group 1;" ::: "memory")
#define CP_WAIT2()  asm volatile("cp.async.wait_group 2;" ::: "memory")

// ---------------------------------------------------------------------------
// Kernel 1: L2-normalize prototypes -> bf16, zero-pad rows [1000,1024)
// ---------------------------------------------------------------------------
__global__ void norm_protos_kernel(const float* __restrict__ proto) {
    int gtid = blockIdx.x * blockDim.x + threadIdx.x;
    int row  = gtid >> 5;
    int lane = gtid & 31;
    if (row >= C_PAD) return;

    if (row >= C_COLS) {
        uint4 z = {0u, 0u, 0u, 0u};
        reinterpret_cast<uint4*>(g_Pn)[row * (F_DIM/8) + lane] = z;
        return;
    }
    const float4* src = reinterpret_cast<const float4*>(proto + (size_t)row * F_DIM);
    float4 v0 = src[lane * 2 + 0];
    float4 v1 = src[lane * 2 + 1];

    float ss = v0.x*v0.x + v0.y*v0.y + v0.z*v0.z + v0.w*v0.w
             + v1.x*v1.x + v1.y*v1.y + v1.z*v1.z + v1.w*v1.w;
    #pragma unroll
    for (int o = 16; o; o >>= 1) ss += __shfl_xor_sync(0xFFFFFFFFu, ss, o);
    float inv = 1.0f / fmaxf(sqrtf(ss), 1e-12f);

    union { __nv_bfloat162 h[4]; uint4 u; } pack;
    pack.h[0] = __floats2bfloat162_rn(v0.x*inv, v0.y*inv);
    pack.h[1] = __floats2bfloat162_rn(v0.z*inv, v0.w*inv);
    pack.h[2] = __floats2bfloat162_rn(v1.x*inv, v1.y*inv);
    pack.h[3] = __floats2bfloat162_rn(v1.z*inv, v1.w*inv);
    reinterpret_cast<uint4*>(g_Pn)[row * (F_DIM/8) + lane] = pack.u;
}

// ---------------------------------------------------------------------------
// Kernel 2: fused normalize(A) + GEMM + epilogue (R9 structure + deep pipeline)
//   - B streamed through a 3-deep cp.async ring (wait_group 1 -> loads stay
//     ~2 chunks ahead; barrier wait is nearly free).
//   - ldsm fragments double-buffered across k-steps (RAW latency hidden).
// ---------------------------------------------------------------------------
__global__ void __launch_bounds__(THREADS, 1)
fused_gemm_kernel(const float* __restrict__ feat,
                  const float* __restrict__ dscale, const float* __restrict__ temp,
                  float* __restrict__ out) {
    extern __shared__ __align__(16) unsigned char smem[];
    const uint32_t smem_base = smem_u32(smem);

    const int tid  = threadIdx.x;
    const int lane = tid & 31;
    const int warp = tid >> 5;
    const int mt   = warp & 1;     // 0/1 -> rows 0-15 / 16-31
    const int s    = warp >> 1;    // col strip 0..7 (16 cols within each chunk)

    float* srow = reinterpret_cast<float*>(smem + SM_SROW);
    if (tid < BM) srow[tid] = 0.0f;

    const uint32_t bufs[3] = { smem_base + SM_B0, smem_base + SM_B1, smem_base + SM_B2 };
    const uint4* gB = reinterpret_cast<const uint4*>(g_Pn);

    // ---- Preload B chunks 0,1,2 (3 commit groups) ----
    #pragma unroll
    for (int pj = 0; pj < 3; pj++) {
        #pragma unroll
        for (int it = 0; it < 8; it++) {
            int idx = it * THREADS + tid;            // 0..4095
            int r = idx >> 5, c = idx & 31;
            CP_ASYNC16(bufs[pj] + r * 512 + ((c ^ (r & 7)) << 4),
                       gB + (size_t)(pj * BNC + r) * 32 + c);
        }
        CP_COMMIT();
    }

    // ---- Normalize A rows in-CTA (overlaps the preloads) ----
    {
        const float4* gF = reinterpret_cast<const float4*>(feat)
                         + (size_t)blockIdx.x * BM * (F_DIM / 4);
        #pragma unroll
        for (int rr = 0; rr < 2; rr++) {
            int r = warp * 2 + rr;
            float4 v0 = __ldg(&gF[r * 64 + lane * 2 + 0]);
            float4 v1 = __ldg(&gF[r * 64 + lane * 2 + 1]);
            float ss = v0.x*v0.x + v0.y*v0.y + v0.z*v0.z + v0.w*v0.w
                     + v1.x*v1.x + v1.y*v1.y + v1.z*v1.z + v1.w*v1.w;
            #pragma unroll
            for (int o = 16; o; o >>= 1) ss += __shfl_xor_sync(0xFFFFFFFFu, ss, o);
            float inv = 1.0f / fmaxf(sqrtf(ss), 1e-12f);

            union { __nv_bfloat162 h[4]; uint4 u; } pack;
            pack.h[0] = __floats2bfloat162_rn(v0.x*inv, v0.y*inv);
            pack.h[1] = __floats2bfloat162_rn(v0.z*inv, v0.w*inv);
            pack.h[2] = __floats2bfloat162_rn(v1.x*inv, v1.y*inv);
            pack.h[3] = __floats2bfloat162_rn(v1.z*inv, v1.w*inv);
            *reinterpret_cast<uint4*>(smem + SM_A + r * 512 + ((lane ^ (r & 7)) << 4)) = pack.u;
        }
    }
    CP_WAIT2();        // chunk 0 resident (1,2 may be in flight)
    __syncthreads();

    // ---- ldsm lane addressing ----
    const int a_row = mt * 16 + (lane & 15);
    const int a_h   = lane >> 4;
    const uint32_t aBase = smem_base + SM_A + a_row * 512;
    const int aXor = a_row & 7;

    const int b_n = (lane & 7) | ((lane & 16) >> 1);   // 0..15 within strip
    const int b_h = (lane >> 3) & 1;
    const int n_row = s * 16 + b_n;
    const uint32_t bRowOff = (uint32_t)(n_row * 512);
    const int bXor = n_row & 7;

    float acc[NCHUNK][2][4];
    #pragma unroll
    for (int j = 0; j < NCHUNK; j++)
        #pragma unroll
        for (int t = 0; t < 2; t++)
            #pragma unroll
            for (int i = 0; i < 4; i++) acc[j][t][i] = 0.0f;

    // ---- fragment double-buffer: preload (chunk 0, k=0) ----
    uint32_t afc[4], bfc[4], afn[4], bfn[4];
    ldsm_x4(afc, aBase + ((a_h ^ aXor) << 4));
    ldsm_x4(bfc, bufs[0] + bRowOff + ((b_h ^ bXor) << 4));

    // ---- Main loop: 8 chunks through the 3-buffer ring ----
    #pragma unroll
    for (int j = 0; j < NCHUNK; j++) {
        const uint32_t bBase = bufs[j % 3] + bRowOff;

        #pragma unroll
        for (int k = 0; k < 16; k++) {
            if (k < 15) {
                ldsm_x4(afn, aBase + (((2 * (k + 1) + a_h) ^ aXor) << 4));
                ldsm_x4(bfn, bBase + (((2 * (k + 1) + b_h) ^ bXor) << 4));
            }
            mma16816(acc[j][0], afc, bfc[0], bfc[1]);
            mma16816(acc[j][1], afc, bfc[2], bfc[3]);
            #pragma unroll
            for (int q = 0; q < 4; q++) { afc[q] = afn[q]; bfc[q] = bfn[q]; }
        }

        if (j < NCHUNK - 1) {
            // chunk j+1 was issued >=2 chunks ago; keep at most one load in flight
            if (j < NCHUNK - 2) CP_WAIT1(); else CP_WAIT0();
            __syncthreads();    // (a) buf j%3 free for reuse, (b) chunk j+1 visible
            if (j + 3 < NCHUNK) {
                uint32_t nb = bufs[j % 3];
                #pragma unroll
                for (int it = 0; it < 8; it++) {
                    int idx = it * THREADS + tid;
                    int r = idx >> 5, c = idx & 31;
                    CP_ASYNC16(nb + r * 512 + ((c ^ (r & 7)) << 4),
                               gB + (size_t)((j + 3) * BNC + r) * 32 + c);
                }
                CP_COMMIT();
            }
            // preload frags for (j+1, k=0)
            ldsm_x4(afc, aBase + ((a_h ^ aXor) << 4));
            ldsm_x4(bfc, bufs[(j + 1) % 3] + bRowOff + ((b_h ^ bXor) << 4));
        }
    }

    // ---- Epilogue phase 1: iso + masked row sums ----
    const float ads = fabsf(__ldg(dscale));
    const float it_ = 1.0f / __ldg(temp);
    const int tr = lane >> 2;            // 0..7
    const int tc = (lane & 3) * 2;       // 0,2,4,6

    float rs0 = 0.0f, rs1 = 0.0f;
    #pragma unroll
    for (int j = 0; j < NCHUNK; j++) {
        #pragma unroll
        for (int t = 0; t < 2; t++) {
            int cb = j * 128 + s * 16 + t * 8 + tc;
            float i0 = ads * fsqrt_ap(fmaxf(1.0f - acc[j][t][0], 0.0f));
            float i1 = ads * fsqrt_ap(fmaxf(1.0f - acc[j][t][1], 0.0f));
            float i2 = ads * fsqrt_ap(fmaxf(1.0f - acc[j][t][2], 0.0f));
            float i3 = ads * fsqrt_ap(fmaxf(1.0f - acc[j][t][3], 0.0f));
            acc[j][t][0] = i0; acc[j][t][1] = i1;
            acc[j][t][2] = i2; acc[j][t][3] = i3;
            if (cb < C_COLS) {            // cb even, C_COLS even: pair never straddles
                rs0 += i0 + i1;
                rs1 += i2 + i3;
            }
        }
    }
    rs0 += __shfl_xor_sync(0xFFFFFFFFu, rs0, 1);
    rs0 += __shfl_xor_sync(0xFFFFFFFFu, rs0, 2);
    rs1 += __shfl_xor_sync(0xFFFFFFFFu, rs1, 1);
    rs1 += __shfl_xor_sync(0xFFFFFFFFu, rs1, 2);
    if ((lane & 3) == 0) {
        atomicAdd(&srow[mt * 16 + tr], rs0);
        atomicAdd(&srow[mt * 16 + tr + 8], rs1);
    }
    __syncthreads();

    // ---- Epilogue phase 2: direct global float2 stores ----
    const float m0 = srow[mt * 16 + tr]     * (1.0f / (float)C_COLS);
    const float m1 = srow[mt * 16 + tr + 8] * (1.0f / (float)C_COLS);
    const size_t grow0 = (size_t)blockIdx.x * BM;
    float* out_r0 = out + (grow0 + mt * 16 + tr)     * C_COLS;
    float* out_r1 = out + (grow0 + mt * 16 + tr + 8) * C_COLS;

    #pragma unroll
    for (int j = 0; j < NCHUNK; j++) {
        #pragma unroll
        for (int t = 0; t < 2; t++) {
            int cb = j * 128 + s * 16 + t * 8 + tc;
            if (cb < C_COLS) {
                float2 w0 = { -(acc[j][t][0] + m0) * it_, -(acc[j][t][1] + m0) * it_ };
                float2 w1 = { -(acc[j][t][2] + m1) * it_, -(acc[j][t][3] + m1) * it_ };
                *reinterpret_cast<float2*>(out_r0 + cb) = w0;
                *reinterpret_cast<float2*>(out_r1 + cb) = w1;
            }
        }
    }
}

// ---------------------------------------------------------------------------
extern "C" void kernel_launch(void* const* d_in, const int* in_sizes, int n_in,
                              void* d_out, int out_size) {
    const float* feat  = (const float*)d_in[0];
    const float* proto = (const float*)d_in[1];
    const float* dsc   = (const float*)d_in[2];
    const float* temp  = (const float*)d_in[3];
    float* out = (float*)d_out;

    cudaFuncSetAttribute(fused_gemm_kernel,
                         cudaFuncAttributeMaxDynamicSharedMemorySize, SM_TOTAL);

    norm_protos_kernel<<<C_PAD / 8, 256>>>(proto);
    fused_gemm_kernel<<<B_ROWS / BM, THREADS, SM_TOTAL>>>(feat, dsc, temp, out);
}